// round 4
// baseline (speedup 1.0000x reference)
#include <cuda_runtime.h>
#include <math.h>

// ---------------- problem constants ----------------
#define BB    2
#define TT    1024
#define DD    768
#define HH    12
#define KVHH  4
#define HDIM  64
#define KVDIM 256
#define LLAY  6
#define VV    32000
#define DFF   3072
#define NROWS (BB*TT)

// ---------------- device scratch (no allocs allowed) ----------------
__device__ float g_X [NROWS*DD];
__device__ float g_X0[NROWS*DD];
__device__ float g_XN[NROWS*DD];
__device__ float g_Q [NROWS*DD];
__device__ float g_K [NROWS*KVDIM];
__device__ float g_V [NROWS*KVDIM];
__device__ float g_Y [NROWS*DD];
__device__ float g_H [NROWS*DFF];
__device__ float g_COS[TT*32];
__device__ float g_SIN[TT*32];

// ---------------- rotary tables ----------------
__global__ void rotary_kernel() {
    int i = blockIdx.x * blockDim.x + threadIdx.x;
    if (i >= TT*32) return;
    int t = i >> 5, c = i & 31;
    double inv = exp(-((double)(2*c) / 64.0) * log(10000.0));
    double a = (double)t * inv;
    g_COS[i] = (float)cos(a);
    g_SIN[i] = (float)sin(a);
}

// ---------------- embedding + RMSnorm (x and x0) ----------------
__global__ void embed_norm_kernel(const int* __restrict__ idx,
                                  const float* __restrict__ wte) {
    int r = blockIdx.x;
    int t = threadIdx.x;
    const float* w = wte + (size_t)idx[r] * DD;
    float v0 = w[t], v1 = w[t+256], v2 = w[t+512];
    __shared__ float red[256];
    red[t] = v0*v0 + v1*v1 + v2*v2;
    __syncthreads();
    for (int s = 128; s > 0; s >>= 1) {
        if (t < s) red[t] += red[t+s];
        __syncthreads();
    }
    float sc = rsqrtf(red[0] / DD + 1e-6f);
    float* x  = g_X  + (size_t)r*DD;
    float* x0 = g_X0 + (size_t)r*DD;
    x[t]      = v0*sc;  x0[t]      = v0*sc;
    x[t+256]  = v1*sc;  x0[t+256]  = v1*sc;
    x[t+512]  = v2*sc;  x0[t+512]  = v2*sc;
}

// ---------------- residual mix + RMSnorm (layer >= 0) or pure norm (layer = -1) ----------------
__global__ void resid_norm_kernel(const float* __restrict__ lamR,
                                  const float* __restrict__ lamX, int layer) {
    int r = blockIdx.x;
    int t = threadIdx.x;
    float rl = 1.f, xl = 0.f;
    bool wr = (layer >= 0);
    if (wr) { rl = lamR[layer]; xl = lamX[layer]; }
    float* x  = g_X  + (size_t)r*DD;
    float* x0 = g_X0 + (size_t)r*DD;
    float* xn = g_XN + (size_t)r*DD;
    float v[3]; float ss = 0.f;
    #pragma unroll
    for (int p = 0; p < 3; p++) {
        int c = t + p*256;
        float v_ = rl * x[c] + xl * x0[c];
        v[p] = v_;
        ss += v_*v_;
    }
    __shared__ float red[256];
    red[t] = ss;
    __syncthreads();
    for (int s = 128; s > 0; s >>= 1) {
        if (t < s) red[t] += red[t+s];
        __syncthreads();
    }
    float sc = rsqrtf(red[0] / DD + 1e-6f);
    #pragma unroll
    for (int p = 0; p < 3; p++) {
        int c = t + p*256;
        if (wr) x[c] = v[p];
        xn[c] = v[p] * sc;
    }
}

// ---------------- generic NT SGEMM: C[M,N] (+)= A[M,K] * B[N,K]^T ----------------
// 64x64 block, 4x4 microtile per thread (vector LDS.128), software-pipelined
// global->reg prefetch of the next k-tile overlapping compute.
// epi: 0 none, 1 relu^2, 2 softcap tanh. Dims: M%64==0, N%64==0, K%16==0.
__global__ void __launch_bounds__(256)
sgemm_nt(const float* __restrict__ A, const float* __restrict__ B,
         float* __restrict__ C, int M, int N, int K,
         int accum, int epi) {
    __shared__ float As[16][64];
    __shared__ float Bs[16][64];
    int tid = threadIdx.x;
    int tx = tid & 15, ty = tid >> 4;
    int row0 = blockIdx.y * 64, col0 = blockIdx.x * 64;

    // per-thread tile-load coordinates (4 elems of A, 4 of B per k-tile)
    int rr[4], kk[4];
    #pragma unroll
    for (int p = 0; p < 4; p++) {
        int e = tid + p*256;
        rr[p] = e >> 4; kk[p] = e & 15;
    }

    float acc[4][4];
    #pragma unroll
    for (int i = 0; i < 4; i++)
        #pragma unroll
        for (int j = 0; j < 4; j++) acc[i][j] = 0.f;

    float pa[4], pb[4];
    #pragma unroll
    for (int p = 0; p < 4; p++) {
        pa[p] = A[(size_t)(row0 + rr[p])*K + kk[p]];
        pb[p] = B[(size_t)(col0 + rr[p])*K + kk[p]];
    }

    for (int k0 = 0; k0 < K; k0 += 16) {
        #pragma unroll
        for (int p = 0; p < 4; p++) {
            As[kk[p]][rr[p]] = pa[p];
            Bs[kk[p]][rr[p]] = pb[p];
        }
        __syncthreads();
        if (k0 + 16 < K) {
            #pragma unroll
            for (int p = 0; p < 4; p++) {
                pa[p] = A[(size_t)(row0 + rr[p])*K + k0 + 16 + kk[p]];
                pb[p] = B[(size_t)(col0 + rr[p])*K + k0 + 16 + kk[p]];
            }
        }
        #pragma unroll
        for (int k = 0; k < 16; k++) {
            float4 a4 = *(const float4*)&As[k][ty*4];
            float4 b4 = *(const float4*)&Bs[k][tx*4];
            float a[4] = {a4.x, a4.y, a4.z, a4.w};
            float b[4] = {b4.x, b4.y, b4.z, b4.w};
            #pragma unroll
            for (int i = 0; i < 4; i++)
                #pragma unroll
                for (int j = 0; j < 4; j++) acc[i][j] += a[i]*b[j];
        }
        __syncthreads();
    }
    #pragma unroll
    for (int i = 0; i < 4; i++) {
        #pragma unroll
        for (int j = 0; j < 4; j++) {
            size_t ci = (size_t)(row0 + ty*4 + i)*N + (col0 + tx*4 + j);
            float v = acc[i][j];
            if (accum) v += C[ci];
            if (epi == 1)      { v = v > 0.f ? v*v : 0.f; }
            else if (epi == 2) { v = 15.f * tanhf(v * (1.f/15.f)); }
            C[ci] = v;
        }
    }
}

// ---------------- value-embedding gate: v += 2*sigmoid(xn[:32]·g_h) * ve_table[idx] ----------------
__global__ void ve_kernel(int j, const int* __restrict__ idx,
                          const float* __restrict__ vet,
                          const float* __restrict__ veg) {
    int r = blockIdx.x;
    int h = threadIdx.x >> 5, lane = threadIdx.x & 31;
    float g = g_XN[(size_t)r*DD + lane] * veg[((size_t)j*KVHH + h)*32 + lane];
    #pragma unroll
    for (int o = 16; o > 0; o >>= 1) g += __shfl_xor_sync(0xffffffffu, g, o);
    float gate = 2.f / (1.f + expf(-g));
    const float* ve = vet + ((size_t)j*VV + idx[r])*KVDIM + h*HDIM;
    float* vp = g_V + (size_t)r*KVDIM + h*HDIM;
    vp[lane]      += gate * ve[lane];
    vp[lane + 32] += gate * ve[lane + 32];
}

// ---------------- RoPE + per-head RMSnorm on Q (warps 0..11) and K (warps 12..15) ----------------
__global__ void rope_norm_kernel() {
    int r = blockIdx.x;
    int w = threadIdx.x >> 5, lane = threadIdx.x & 31;
    float* ptr;
    if (w < HH) ptr = g_Q + (size_t)r*DD    + w*HDIM;
    else        ptr = g_K + (size_t)r*KVDIM + (w - HH)*HDIM;
    int t = r % TT;   // row index within batch = position
    float c = g_COS[t*32 + lane], s = g_SIN[t*32 + lane];
    float x1 = ptr[lane], x2 = ptr[lane + 32];
    float a =  x1*c + x2*s;
    float b = -x1*s + x2*c;
    float ss = a*a + b*b;
    #pragma unroll
    for (int o = 16; o > 0; o >>= 1) ss += __shfl_xor_sync(0xffffffffu, ss, o);
    float sc = rsqrtf(ss / HDIM + 1e-6f);
    ptr[lane]      = a * sc;
    ptr[lane + 32] = b * sc;
}

// ---------------- sliding-window causal attention, one block per (b,h,pos) ----------------
__global__ void attn_kernel(int win) {
    int b = blockIdx.z, h = blockIdx.y, pos = blockIdx.x;
    int kvh = h / (HH / KVHH);
    int lo = pos - win + 1; if (lo < 0) lo = 0;
    int n = pos - lo + 1;
    __shared__ float sc[TT];
    __shared__ float qv[HDIM];
    __shared__ float red[128];
    int tid = threadIdx.x;
    if (tid < HDIM) qv[tid] = g_Q[(size_t)(b*TT + pos)*DD + h*HDIM + tid];
    __syncthreads();

    float mx = -1e30f;
    for (int jj = tid; jj < n; jj += 128) {
        const float4* kp = (const float4*)(g_K + (size_t)(b*TT + lo + jj)*KVDIM + kvh*HDIM);
        float d = 0.f;
        #pragma unroll
        for (int c = 0; c < 16; c++) {
            float4 k4 = kp[c];
            d += qv[4*c]*k4.x + qv[4*c+1]*k4.y + qv[4*c+2]*k4.z + qv[4*c+3]*k4.w;
        }
        d *= 0.125f;
        sc[jj] = d;
        mx = fmaxf(mx, d);
    }
    red[tid] = mx;
    __syncthreads();
    for (int s = 64; s > 0; s >>= 1) {
        if (tid < s) red[tid] = fmaxf(red[tid], red[tid+s]);
        __syncthreads();
    }
    mx = red[0];
    __syncthreads();

    float ls = 0.f;
    for (int jj = tid; jj < n; jj += 128) {
        float e = expf(sc[jj] - mx);
        sc[jj] = e;
        ls += e;
    }
    red[tid] = ls;
    __syncthreads();
    for (int s = 64; s > 0; s >>= 1) {
        if (tid < s) red[tid] += red[tid+s];
        __syncthreads();
    }
    float inv = 1.f / red[0];
    __syncthreads();

    // PV: 2 threads per channel (even/odd keys), combined via smem
    {
        int c = tid & 63, half = tid >> 6;
        float acc = 0.f;
        const float* vp = g_V + (size_t)(b*TT + lo)*KVDIM + kvh*HDIM + c;
        #pragma unroll 4
        for (int jj = half; jj < n; jj += 2) acc += sc[jj] * vp[(size_t)jj*KVDIM];
        red[tid] = acc;
        __syncthreads();
        if (tid < 64) {
            g_Y[(size_t)(b*TT + pos)*DD + h*HDIM + tid] =
                (red[tid] + red[tid + 64]) * inv;
        }
    }
}

// ---------------- host driver ----------------
extern "C" void kernel_launch(void* const* d_in, const int* in_sizes, int n_in,
                              void* d_out, int out_size) {
    const int*   idx  = (const int*)  d_in[0];
    const float* wte  = (const float*)d_in[1];
    const float* Wq   = (const float*)d_in[2];
    const float* Wk   = (const float*)d_in[3];
    const float* Wv   = (const float*)d_in[4];
    const float* Wo   = (const float*)d_in[5];
    const float* Wfc  = (const float*)d_in[6];
    const float* Wpr  = (const float*)d_in[7];
    const float* vet  = (const float*)d_in[8];
    const float* veg  = (const float*)d_in[9];
    const float* lamR = (const float*)d_in[10];
    const float* lamX = (const float*)d_in[11];
    const float* lmw  = (const float*)d_in[12];
    float* out = (float*)d_out;

    float *X, *XN, *Q, *K, *Vb, *Y, *Hb;
    cudaGetSymbolAddress((void**)&X,  g_X);
    cudaGetSymbolAddress((void**)&XN, g_XN);
    cudaGetSymbolAddress((void**)&Q,  g_Q);
    cudaGetSymbolAddress((void**)&K,  g_K);
    cudaGetSymbolAddress((void**)&Vb, g_V);
    cudaGetSymbolAddress((void**)&Y,  g_Y);
    cudaGetSymbolAddress((void**)&Hb, g_H);

    static const int WINDOWS[LLAY] = {TT/2, TT, TT/2, TT, TT/2, TT};

    rotary_kernel<<<(TT*32 + 255)/256, 256>>>();
    embed_norm_kernel<<<NROWS, 256>>>(idx, wte);

    for (int i = 0; i < LLAY; i++) {
        // x = rl*x + xl*x0 ; xn = norm(x)
        resid_norm_kernel<<<NROWS, 256>>>(lamR, lamX, i);
        // q,k,v projections
        sgemm_nt<<<dim3(DD/64,    NROWS/64), 256>>>(XN, Wq + (size_t)i*DD*DD,     Q,  NROWS, DD,    DD, 0, 0);
        sgemm_nt<<<dim3(KVDIM/64, NROWS/64), 256>>>(XN, Wk + (size_t)i*KVDIM*DD,  K,  NROWS, KVDIM, DD, 0, 0);
        sgemm_nt<<<dim3(KVDIM/64, NROWS/64), 256>>>(XN, Wv + (size_t)i*KVDIM*DD,  Vb, NROWS, KVDIM, DD, 0, 0);
        // value embeddings on layers 1,3,5
        if (i == 1 || i == 3 || i == 5) {
            int j = (i - 1) / 2;
            ve_kernel<<<NROWS, KVHH*32>>>(j, idx, vet, veg);
        }
        // rope + per-head norm on q,k
        rope_norm_kernel<<<NROWS, (HH + KVHH)*32>>>();
        // attention
        attn_kernel<<<dim3(TT, HH, BB), 128>>>(WINDOWS[i]);
        // x += y @ Wo^T
        sgemm_nt<<<dim3(DD/64, NROWS/64), 256>>>(Y, Wo + (size_t)i*DD*DD, X, NROWS, DD, DD, 1, 0);
        // xn2 = norm(x)
        resid_norm_kernel<<<NROWS, 256>>>(lamR, lamX, -1);
        // h = relu(xn2 @ Wfc^T)^2   (fused epilogue)
        sgemm_nt<<<dim3(DFF/64, NROWS/64), 256>>>(XN, Wfc + (size_t)i*DFF*DD, Hb, NROWS, DFF, DD, 0, 1);
        // x += h @ Wproj^T
        sgemm_nt<<<dim3(DD/64, NROWS/64), 256>>>(Hb, Wpr + (size_t)i*DD*DFF, X, NROWS, DD, DFF, 1, 0);
    }

    // final norm + lm head with softcap epilogue
    resid_norm_kernel<<<NROWS, 256>>>(lamR, lamX, -1);
    sgemm_nt<<<dim3(VV/64, NROWS/64), 256>>>(XN, lmw, out, NROWS, VV, DD, 0, 2);
}

// round 9
// speedup vs baseline: 2.1656x; 2.1656x over previous
#include <cuda_runtime.h>
#include <math.h>

// ---------------- problem constants ----------------
#define BB    2
#define TT    1024
#define DD    768
#define HH    12
#define KVHH  4
#define HDIM  64
#define KVDIM 256
#define LLAY  6
#define VV    32000
#define DFF   3072
#define NROWS (BB*TT)
#define QT    64
#define KT    32

// ---------------- device scratch (no allocs allowed) ----------------
__device__ float g_X [NROWS*DD];
__device__ float g_X0[NROWS*DD];
__device__ float g_XN[NROWS*DD];
__device__ float g_Q [NROWS*DD];
__device__ float g_K [NROWS*KVDIM];
__device__ float g_V [NROWS*KVDIM];
__device__ float g_Y [NROWS*DD];
__device__ float g_H [NROWS*DFF];
__device__ float g_COS[TT*32];
__device__ float g_SIN[TT*32];

// ---------------- rotary tables ----------------
__global__ void rotary_kernel() {
    int i = blockIdx.x * blockDim.x + threadIdx.x;
    if (i >= TT*32) return;
    int t = i >> 5, c = i & 31;
    double inv = exp(-((double)(2*c) / 64.0) * log(10000.0));
    double a = (double)t * inv;
    g_COS[i] = (float)cos(a);
    g_SIN[i] = (float)sin(a);
}

// ---------------- embedding + RMSnorm (x and x0) ----------------
__global__ void embed_norm_kernel(const int* __restrict__ idx,
                                  const float* __restrict__ wte) {
    int r = blockIdx.x;
    int t = threadIdx.x;
    const float* w = wte + (size_t)idx[r] * DD;
    float v0 = w[t], v1 = w[t+256], v2 = w[t+512];
    __shared__ float red[256];
    red[t] = v0*v0 + v1*v1 + v2*v2;
    __syncthreads();
    for (int s = 128; s > 0; s >>= 1) {
        if (t < s) red[t] += red[t+s];
        __syncthreads();
    }
    float sc = rsqrtf(red[0] / DD + 1e-6f);
    float* x  = g_X  + (size_t)r*DD;
    float* x0 = g_X0 + (size_t)r*DD;
    x[t]      = v0*sc;  x0[t]      = v0*sc;
    x[t+256]  = v1*sc;  x0[t+256]  = v1*sc;
    x[t+512]  = v2*sc;  x0[t+512]  = v2*sc;
}

// ---------------- residual mix + RMSnorm (layer >= 0) or pure norm (layer = -1) ----------------
__global__ void resid_norm_kernel(const float* __restrict__ lamR,
                                  const float* __restrict__ lamX, int layer) {
    int r = blockIdx.x;
    int t = threadIdx.x;
    float rl = 1.f, xl = 0.f;
    bool wr = (layer >= 0);
    if (wr) { rl = lamR[layer]; xl = lamX[layer]; }
    float* x  = g_X  + (size_t)r*DD;
    float* x0 = g_X0 + (size_t)r*DD;
    float* xn = g_XN + (size_t)r*DD;
    float v[3]; float ss = 0.f;
    #pragma unroll
    for (int p = 0; p < 3; p++) {
        int c = t + p*256;
        float v_ = rl * x[c] + xl * x0[c];
        v[p] = v_;
        ss += v_*v_;
    }
    __shared__ float red[256];
    red[t] = ss;
    __syncthreads();
    for (int s = 128; s > 0; s >>= 1) {
        if (t < s) red[t] += red[t+s];
        __syncthreads();
    }
    float sc = rsqrtf(red[0] / DD + 1e-6f);
    #pragma unroll
    for (int p = 0; p < 3; p++) {
        int c = t + p*256;
        if (wr) x[c] = v[p];
        xn[c] = v[p] * sc;
    }
}

// ---------------- core 128x128 GEMM tile: C[row0:+128, col0:+128] (+)= A*B^T ----------------
__device__ __forceinline__ void gemm_tile_128(
    const float* __restrict__ A, const float* __restrict__ B,
    float* __restrict__ C, int N, int K, int row0, int col0,
    int accum, int epi)
{
    __shared__ float As[16][128];
    __shared__ float Bs[16][128];
    int tid = threadIdx.x;
    int tx = tid & 15, ty = tid >> 4;

    int lr[2], lc[2];
    #pragma unroll
    for (int p = 0; p < 2; p++) {
        int e = tid + p*256;
        lr[p] = e >> 2;
        lc[p] = e & 3;
    }

    float acc[8][8];
    #pragma unroll
    for (int i = 0; i < 8; i++)
        #pragma unroll
        for (int j = 0; j < 8; j++) acc[i][j] = 0.f;

    float4 pa[2], pb[2];
    #pragma unroll
    for (int p = 0; p < 2; p++) {
        pa[p] = *(const float4*)&A[(size_t)(row0 + lr[p])*K + lc[p]*4];
        pb[p] = *(const float4*)&B[(size_t)(col0 + lr[p])*K + lc[p]*4];
    }

    for (int k0 = 0; k0 < K; k0 += 16) {
        #pragma unroll
        for (int p = 0; p < 2; p++) {
            int kb = lc[p]*4, r = lr[p];
            As[kb+0][r] = pa[p].x; As[kb+1][r] = pa[p].y;
            As[kb+2][r] = pa[p].z; As[kb+3][r] = pa[p].w;
            Bs[kb+0][r] = pb[p].x; Bs[kb+1][r] = pb[p].y;
            Bs[kb+2][r] = pb[p].z; Bs[kb+3][r] = pb[p].w;
        }
        __syncthreads();
        if (k0 + 16 < K) {
            #pragma unroll
            for (int p = 0; p < 2; p++) {
                pa[p] = *(const float4*)&A[(size_t)(row0 + lr[p])*K + k0 + 16 + lc[p]*4];
                pb[p] = *(const float4*)&B[(size_t)(col0 + lr[p])*K + k0 + 16 + lc[p]*4];
            }
        }
        #pragma unroll
        for (int k = 0; k < 16; k++) {
            float4 a0 = *(const float4*)&As[k][ty*8];
            float4 a1 = *(const float4*)&As[k][ty*8+4];
            float4 b0 = *(const float4*)&Bs[k][tx*8];
            float4 b1 = *(const float4*)&Bs[k][tx*8+4];
            float a[8] = {a0.x,a0.y,a0.z,a0.w,a1.x,a1.y,a1.z,a1.w};
            float b[8] = {b0.x,b0.y,b0.z,b0.w,b1.x,b1.y,b1.z,b1.w};
            #pragma unroll
            for (int i = 0; i < 8; i++)
                #pragma unroll
                for (int j = 0; j < 8; j++) acc[i][j] += a[i]*b[j];
        }
        __syncthreads();
    }

    #pragma unroll
    for (int i = 0; i < 8; i++) {
        size_t rb = (size_t)(row0 + ty*8 + i)*N + col0 + tx*8;
        #pragma unroll
        for (int j4 = 0; j4 < 2; j4++) {
            float4 v;
            v.x = acc[i][j4*4+0]; v.y = acc[i][j4*4+1];
            v.z = acc[i][j4*4+2]; v.w = acc[i][j4*4+3];
            float* cp = &C[rb + j4*4];
            if (accum) {
                float4 o = *(const float4*)cp;
                v.x += o.x; v.y += o.y; v.z += o.z; v.w += o.w;
            }
            if (epi == 1) {
                v.x = v.x > 0.f ? v.x*v.x : 0.f;
                v.y = v.y > 0.f ? v.y*v.y : 0.f;
                v.z = v.z > 0.f ? v.z*v.z : 0.f;
                v.w = v.w > 0.f ? v.w*v.w : 0.f;
            } else if (epi == 2) {
                v.x = 15.f * tanhf(v.x * (1.f/15.f));
                v.y = 15.f * tanhf(v.y * (1.f/15.f));
                v.z = 15.f * tanhf(v.z * (1.f/15.f));
                v.w = 15.f * tanhf(v.w * (1.f/15.f));
            }
            *(float4*)cp = v;
        }
    }
}

// generic GEMM kernel: grid = (N/128, M/128)
__global__ void __launch_bounds__(256)
sgemm_nt(const float* __restrict__ A, const float* __restrict__ B,
         float* __restrict__ C, int N, int K, int accum, int epi) {
    gemm_tile_128(A, B, C, N, K, blockIdx.y*128, blockIdx.x*128, accum, epi);
}

// fused QKV: grid = (10, M/128). blocks 0-5 -> Q, 6-7 -> K, 8-9 -> V.
__global__ void __launch_bounds__(256)
qkv_gemm(const float* __restrict__ Wq, const float* __restrict__ Wk,
         const float* __restrict__ Wv) {
    int bx = blockIdx.x, row0 = blockIdx.y*128;
    const float* B; float* C; int N, col0;
    if (bx < 6)      { B = Wq; C = g_Q; N = DD;    col0 = bx*128; }
    else if (bx < 8) { B = Wk; C = g_K; N = KVDIM; col0 = (bx-6)*128; }
    else             { B = Wv; C = g_V; N = KVDIM; col0 = (bx-8)*128; }
    gemm_tile_128(g_XN, B, C, N, DD, row0, col0, 0, 0);
}

// ---------------- value-embedding gate ----------------
__global__ void ve_kernel(int j, const int* __restrict__ idx,
                          const float* __restrict__ vet,
                          const float* __restrict__ veg) {
    int r = blockIdx.x;
    int h = threadIdx.x >> 5, lane = threadIdx.x & 31;
    float g = g_XN[(size_t)r*DD + lane] * veg[((size_t)j*KVHH + h)*32 + lane];
    #pragma unroll
    for (int o = 16; o > 0; o >>= 1) g += __shfl_xor_sync(0xffffffffu, g, o);
    float gate = 2.f / (1.f + expf(-g));
    const float* ve = vet + ((size_t)j*VV + idx[r])*KVDIM + h*HDIM;
    float* vp = g_V + (size_t)r*KVDIM + h*HDIM;
    vp[lane]      += gate * ve[lane];
    vp[lane + 32] += gate * ve[lane + 32];
}

// ---------------- RoPE + per-head RMSnorm ----------------
__global__ void rope_norm_kernel() {
    int r = blockIdx.x;
    int w = threadIdx.x >> 5, lane = threadIdx.x & 31;
    float* ptr;
    if (w < HH) ptr = g_Q + (size_t)r*DD    + w*HDIM;
    else        ptr = g_K + (size_t)r*KVDIM + (w - HH)*HDIM;
    int t = r % TT;
    float c = g_COS[t*32 + lane], s = g_SIN[t*32 + lane];
    float x1 = ptr[lane], x2 = ptr[lane + 32];
    float a =  x1*c + x2*s;
    float b = -x1*s + x2*c;
    float ss = a*a + b*b;
    #pragma unroll
    for (int o = 16; o > 0; o >>= 1) ss += __shfl_xor_sync(0xffffffffu, ss, o);
    float sc = rsqrtf(ss / HDIM + 1e-6f);
    ptr[lane]      = a * sc;
    ptr[lane + 32] = b * sc;
}

// ---------------- tiled sliding-window attention ----------------
// block = (qtile, h, b); 256 threads as 16(ty: 4 queries each) x 16(tx).
// Online softmax over key tiles of KT=32 staged in smem.
__global__ void __launch_bounds__(256)
attn_kernel(int win) {
    int b = blockIdx.z, h = blockIdx.y, q0 = blockIdx.x * QT;
    int kvh = h / (HH / KVHH);
    __shared__ float Qs[QT][64];      // [q][d]
    __shared__ float Ks[KT][66];      // [k][d] padded
    __shared__ float Vs[KT][64];      // [k][c]
    __shared__ float Ps[KT][65];      // [k][q] padded
    int tid = threadIdx.x;
    int tx = tid & 15, ty = tid >> 4;

    // load Q tile (float4 gmem reads, scalar smem writes)
    for (int e = tid; e < QT*16; e += 256) {
        int q = e >> 4, d4 = e & 15;
        float4 v = *(const float4*)&g_Q[(size_t)(b*TT + q0 + q)*DD + h*HDIM + d4*4];
        Qs[q][d4*4+0] = v.x; Qs[q][d4*4+1] = v.y;
        Qs[q][d4*4+2] = v.z; Qs[q][d4*4+3] = v.w;
    }

    float m[4], l[4], o[4][4];
    #pragma unroll
    for (int i = 0; i < 4; i++) {
        m[i] = -1e30f; l[i] = 0.f;
        #pragma unroll
        for (int j = 0; j < 4; j++) o[i][j] = 0.f;
    }

    int klo = q0 - win + 1; if (klo < 0) klo = 0;
    int k_start = klo & ~(KT-1);

    for (int k0 = k_start; k0 < q0 + QT; k0 += KT) {
        // load K (as [k][d]) and V tiles
        for (int e = tid; e < KT*16; e += 256) {
            int k = e >> 4, d4 = e & 15;
            size_t row = (size_t)(b*TT + k0 + k)*KVDIM + kvh*HDIM;
            float4 kv = *(const float4*)&g_K[row + d4*4];
            float4 vv = *(const float4*)&g_V[row + d4*4];
            Ks[k][d4*4+0] = kv.x; Ks[k][d4*4+1] = kv.y;
            Ks[k][d4*4+2] = kv.z; Ks[k][d4*4+3] = kv.w;
            Vs[k][d4*4+0] = vv.x; Vs[k][d4*4+1] = vv.y;
            Vs[k][d4*4+2] = vv.z; Vs[k][d4*4+3] = vv.w;
        }
        __syncthreads();

        // scores fragment: 4 q x 2 k
        float s[4][2];
        #pragma unroll
        for (int i = 0; i < 4; i++) { s[i][0] = 0.f; s[i][1] = 0.f; }
        #pragma unroll 8
        for (int d = 0; d < 64; d++) {
            float k0v = Ks[tx*2+0][d];
            float k1v = Ks[tx*2+1][d];
            #pragma unroll
            for (int i = 0; i < 4; i++) {
                float qv = Qs[ty*4+i][d];
                s[i][0] += qv * k0v;
                s[i][1] += qv * k1v;
            }
        }
        // mask + scale
        #pragma unroll
        for (int i = 0; i < 4; i++) {
            int qg = q0 + ty*4 + i;
            #pragma unroll
            for (int j = 0; j < 2; j++) {
                int kg = k0 + tx*2 + j;
                int diff = qg - kg;
                bool valid = (diff >= 0) && (diff < win);
                s[i][j] = valid ? s[i][j] * 0.125f : -1e30f;
            }
        }
        // online softmax update (per q row, replicated across 16 tx lanes)
        #pragma unroll
        for (int i = 0; i < 4; i++) {
            float tmax = fmaxf(s[i][0], s[i][1]);
            #pragma unroll
            for (int off = 8; off > 0; off >>= 1)
                tmax = fmaxf(tmax, __shfl_xor_sync(0xffffffffu, tmax, off));
            float m_new = fmaxf(m[i], tmax);
            float p0 = (s[i][0] <= -1e29f) ? 0.f : expf(s[i][0] - m_new);
            float p1 = (s[i][1] <= -1e29f) ? 0.f : expf(s[i][1] - m_new);
            float tsum = p0 + p1;
            #pragma unroll
            for (int off = 8; off > 0; off >>= 1)
                tsum += __shfl_xor_sync(0xffffffffu, tsum, off);
            float scale = expf(m[i] - m_new);   // m old=-1e30,new=-1e30 -> exp(0)=1, acc is 0: safe
            l[i] = l[i] * scale + tsum;
            #pragma unroll
            for (int j = 0; j < 4; j++) o[i][j] *= scale;
            m[i] = m_new;
            Ps[tx*2+0][ty*4+i] = p0;
            Ps[tx*2+1][ty*4+i] = p1;
        }
        __syncthreads();

        // PV: o[q][c] += sum_k P[q][k] * V[k][c], c = tx*4+j
        #pragma unroll 4
        for (int kk = 0; kk < KT; kk++) {
            float4 v4 = *(const float4*)&Vs[kk][tx*4];
            #pragma unroll
            for (int i = 0; i < 4; i++) {
                float p = Ps[kk][ty*4+i];
                o[i][0] += p * v4.x;
                o[i][1] += p * v4.y;
                o[i][2] += p * v4.z;
                o[i][3] += p * v4.w;
            }
        }
        __syncthreads();
    }

    #pragma unroll
    for (int i = 0; i < 4; i++) {
        float inv = 1.f / l[i];
        float4 v;
        v.x = o[i][0]*inv; v.y = o[i][1]*inv;
        v.z = o[i][2]*inv; v.w = o[i][3]*inv;
        *(float4*)&g_Y[(size_t)(b*TT + q0 + ty*4 + i)*DD + h*HDIM + tx*4] = v;
    }
}

// ---------------- host driver ----------------
extern "C" void kernel_launch(void* const* d_in, const int* in_sizes, int n_in,
                              void* d_out, int out_size) {
    const int*   idx  = (const int*)  d_in[0];
    const float* wte  = (const float*)d_in[1];
    const float* Wq   = (const float*)d_in[2];
    const float* Wk   = (const float*)d_in[3];
    const float* Wv   = (const float*)d_in[4];
    const float* Wo   = (const float*)d_in[5];
    const float* Wfc  = (const float*)d_in[6];
    const float* Wpr  = (const float*)d_in[7];
    const float* vet  = (const float*)d_in[8];
    const float* veg  = (const float*)d_in[9];
    const float* lamR = (const float*)d_in[10];
    const float* lamX = (const float*)d_in[11];
    const float* lmw  = (const float*)d_in[12];
    float* out = (float*)d_out;

    float *X, *XN, *Y, *Hb;
    cudaGetSymbolAddress((void**)&X,  g_X);
    cudaGetSymbolAddress((void**)&XN, g_XN);
    cudaGetSymbolAddress((void**)&Y,  g_Y);
    cudaGetSymbolAddress((void**)&Hb, g_H);

    static const int WINDOWS[LLAY] = {TT/2, TT, TT/2, TT, TT/2, TT};

    rotary_kernel<<<(TT*32 + 255)/256, 256>>>();
    embed_norm_kernel<<<NROWS, 256>>>(idx, wte);

    for (int i = 0; i < LLAY; i++) {
        resid_norm_kernel<<<NROWS, 256>>>(lamR, lamX, i);
        qkv_gemm<<<dim3(10, NROWS/128), 256>>>(Wq + (size_t)i*DD*DD,
                                               Wk + (size_t)i*KVDIM*DD,
                                               Wv + (size_t)i*KVDIM*DD);
        if (i == 1 || i == 3 || i == 5) {
            int j = (i - 1) / 2;
            ve_kernel<<<NROWS, KVHH*32>>>(j, idx, vet, veg);
        }
        rope_norm_kernel<<<NROWS, (HH + KVHH)*32>>>();
        attn_kernel<<<dim3(TT/QT, HH, BB), 256>>>(WINDOWS[i]);
        sgemm_nt<<<dim3(DD/128, NROWS/128), 256>>>(Y, Wo + (size_t)i*DD*DD, X, DD, DD, 1, 0);
        resid_norm_kernel<<<NROWS, 256>>>(lamR, lamX, -1);
        sgemm_nt<<<dim3(DFF/128, NROWS/128), 256>>>(XN, Wfc + (size_t)i*DFF*DD, Hb, DFF, DD, 0, 1);
        sgemm_nt<<<dim3(DD/128, NROWS/128), 256>>>(Hb, Wpr + (size_t)i*DD*DFF, X, DD, DFF, 1, 0);
    }

    resid_norm_kernel<<<NROWS, 256>>>(lamR, lamX, -1);
    sgemm_nt<<<dim3(VV/128, NROWS/128), 256>>>(XN, lmw, out, VV, DD, 0, 2);
}

// round 12
// speedup vs baseline: 3.0753x; 1.4201x over previous
#include <cuda_runtime.h>
#include <math.h>

// ---------------- problem constants ----------------
#define BB    2
#define TT    1024
#define DD    768
#define HH    12
#define KVHH  4
#define HDIM  64
#define KVDIM 256
#define LLAY  6
#define VV    32000
#define DFF   3072
#define NROWS (BB*TT)
#define QT    64
#define KT    32

// ---------------- device scratch (no allocs allowed) ----------------
__device__ float g_X [NROWS*DD];
__device__ float g_X0[NROWS*DD];
__device__ float g_XN[NROWS*DD];
__device__ float g_Q [NROWS*DD];
__device__ float g_K [NROWS*KVDIM];
__device__ float g_V [NROWS*KVDIM];
__device__ float g_Y [NROWS*DD];
__device__ float g_H [NROWS*DFF];
__device__ float g_COS[TT*32];
__device__ float g_SIN[TT*32];

// ---------------- rotary tables ----------------
__global__ void rotary_kernel() {
    int i = blockIdx.x * blockDim.x + threadIdx.x;
    if (i >= TT*32) return;
    int t = i >> 5, c = i & 31;
    double inv = exp(-((double)(2*c) / 64.0) * log(10000.0));
    double a = (double)t * inv;
    g_COS[i] = (float)cos(a);
    g_SIN[i] = (float)sin(a);
}

// ---------------- embedding + RMSnorm (x and x0) ----------------
__global__ void embed_norm_kernel(const int* __restrict__ idx,
                                  const float* __restrict__ wte) {
    int r = blockIdx.x;
    int t = threadIdx.x;
    const float* w = wte + (size_t)idx[r] * DD;
    float v0 = w[t], v1 = w[t+256], v2 = w[t+512];
    __shared__ float red[256];
    red[t] = v0*v0 + v1*v1 + v2*v2;
    __syncthreads();
    for (int s = 128; s > 0; s >>= 1) {
        if (t < s) red[t] += red[t+s];
        __syncthreads();
    }
    float sc = rsqrtf(red[0] / DD + 1e-6f);
    float* x  = g_X  + (size_t)r*DD;
    float* x0 = g_X0 + (size_t)r*DD;
    x[t]      = v0*sc;  x0[t]      = v0*sc;
    x[t+256]  = v1*sc;  x0[t+256]  = v1*sc;
    x[t+512]  = v2*sc;  x0[t+512]  = v2*sc;
}

// ---------------- residual mix + RMSnorm ----------------
__global__ void resid_norm_kernel(const float* __restrict__ lamR,
                                  const float* __restrict__ lamX, int layer) {
    int r = blockIdx.x;
    int t = threadIdx.x;
    float rl = 1.f, xl = 0.f;
    bool wr = (layer >= 0);
    if (wr) { rl = lamR[layer]; xl = lamX[layer]; }
    float* x  = g_X  + (size_t)r*DD;
    float* x0 = g_X0 + (size_t)r*DD;
    float* xn = g_XN + (size_t)r*DD;
    float v[3]; float ss = 0.f;
    #pragma unroll
    for (int p = 0; p < 3; p++) {
        int c = t + p*256;
        float v_ = rl * x[c] + xl * x0[c];
        v[p] = v_;
        ss += v_*v_;
    }
    __shared__ float red[256];
    red[t] = ss;
    __syncthreads();
    for (int s = 128; s > 0; s >>= 1) {
        if (t < s) red[t] += red[t+s];
        __syncthreads();
    }
    float sc = rsqrtf(red[0] / DD + 1e-6f);
    #pragma unroll
    for (int p = 0; p < 3; p++) {
        int c = t + p*256;
        if (wr) x[c] = v[p];
        xn[c] = v[p] * sc;
    }
}

// ---------------- tf32 helpers ----------------
__device__ __forceinline__ void split_tf32(float x, unsigned& hi, unsigned& lo) {
    unsigned h;
    asm("cvt.rna.tf32.f32 %0, %1;" : "=r"(h) : "f"(x));
    float r = x - __uint_as_float(h);
    unsigned l;
    asm("cvt.rna.tf32.f32 %0, %1;" : "=r"(l) : "f"(r));
    hi = h; lo = l;
}

__device__ __forceinline__ void mma_tf32(float c[4], const unsigned a[4], const unsigned b[2]) {
    asm volatile(
        "mma.sync.aligned.m16n8k8.row.col.f32.tf32.tf32.f32 "
        "{%0,%1,%2,%3}, {%4,%5,%6,%7}, {%8,%9}, {%0,%1,%2,%3};"
        : "+f"(c[0]), "+f"(c[1]), "+f"(c[2]), "+f"(c[3])
        : "r"(a[0]), "r"(a[1]), "r"(a[2]), "r"(a[3]), "r"(b[0]), "r"(b[1]));
}

// ---------------- tensor-core 128x128 GEMM tile (3xTF32): C (+)= A*B^T ----------------
// 256 thr = 8 warps (2 M x 4 N), warp tile 64x32, mma m16n8k8, K-tile 32.
// smem row-major [row][36] (pad 4) -> conflict-free fragment LDS.
// epi: 0 none, 1 relu^2, 2 softcap tanh. Dims: M%128==0, N%128==0, K%32==0.
__device__ __forceinline__ void gemm_tile_tc(
    const float* __restrict__ A, const float* __restrict__ B,
    float* __restrict__ C, int N, int K, int row0, int col0,
    int accum, int epi)
{
    __shared__ float As[128][36];
    __shared__ float Bs[128][36];
    int tid = threadIdx.x;
    int warp = tid >> 5, lane = tid & 31;
    int wm = warp >> 2, wn = warp & 3;           // warp origin (wm*64, wn*32)
    int gid = lane >> 2, tig = lane & 3;

    // loader coords: 128 rows x 8 float4 per matrix = 1024 -> 4 per thread
    int lrow[4], lk4[4];
    #pragma unroll
    for (int p = 0; p < 4; p++) {
        int e = tid + p*256;
        lrow[p] = e >> 3;
        lk4[p]  = e & 7;
    }

    float c[4][4][4];
    #pragma unroll
    for (int mt = 0; mt < 4; mt++)
        #pragma unroll
        for (int nt = 0; nt < 4; nt++)
            #pragma unroll
            for (int r = 0; r < 4; r++) c[mt][nt][r] = 0.f;

    float4 pa[4], pb[4];
    #pragma unroll
    for (int p = 0; p < 4; p++) {
        pa[p] = *(const float4*)&A[(size_t)(row0 + lrow[p])*K + lk4[p]*4];
        pb[p] = *(const float4*)&B[(size_t)(col0 + lrow[p])*K + lk4[p]*4];
    }

    for (int k0 = 0; k0 < K; k0 += 32) {
        #pragma unroll
        for (int p = 0; p < 4; p++) {
            *(float4*)&As[lrow[p]][lk4[p]*4] = pa[p];
            *(float4*)&Bs[lrow[p]][lk4[p]*4] = pb[p];
        }
        __syncthreads();
        if (k0 + 32 < K) {
            #pragma unroll
            for (int p = 0; p < 4; p++) {
                pa[p] = *(const float4*)&A[(size_t)(row0 + lrow[p])*K + k0 + 32 + lk4[p]*4];
                pb[p] = *(const float4*)&B[(size_t)(col0 + lrow[p])*K + k0 + 32 + lk4[p]*4];
            }
        }
        #pragma unroll
        for (int kb = 0; kb < 32; kb += 8) {
            unsigned ah[4][4], al[4][4], bh[4][2], bl[4][2];
            #pragma unroll
            for (int mt = 0; mt < 4; mt++) {
                int r = wm*64 + mt*16 + gid;
                split_tf32(As[r  ][kb+tig  ], ah[mt][0], al[mt][0]);
                split_tf32(As[r+8][kb+tig  ], ah[mt][1], al[mt][1]);
                split_tf32(As[r  ][kb+tig+4], ah[mt][2], al[mt][2]);
                split_tf32(As[r+8][kb+tig+4], ah[mt][3], al[mt][3]);
            }
            #pragma unroll
            for (int nt = 0; nt < 4; nt++) {
                int r = wn*32 + nt*8 + gid;
                split_tf32(Bs[r][kb+tig  ], bh[nt][0], bl[nt][0]);
                split_tf32(Bs[r][kb+tig+4], bh[nt][1], bl[nt][1]);
            }
            #pragma unroll
            for (int mt = 0; mt < 4; mt++)
                #pragma unroll
                for (int nt = 0; nt < 4; nt++) {
                    mma_tf32(c[mt][nt], ah[mt], bh[nt]);
                    mma_tf32(c[mt][nt], al[mt], bh[nt]);
                    mma_tf32(c[mt][nt], ah[mt], bl[nt]);
                }
        }
        __syncthreads();
    }

    // epilogue
    #pragma unroll
    for (int mt = 0; mt < 4; mt++) {
        int rbase = row0 + wm*64 + mt*16 + gid;
        #pragma unroll
        for (int nt = 0; nt < 4; nt++) {
            int cc = col0 + wn*32 + nt*8 + tig*2;
            #pragma unroll
            for (int h = 0; h < 2; h++) {
                int r = rbase + h*8;
                float v0 = c[mt][nt][h*2+0];
                float v1 = c[mt][nt][h*2+1];
                float* cp = &C[(size_t)r*N + cc];
                if (accum) { v0 += cp[0]; v1 += cp[1]; }
                if (epi == 1) {
                    v0 = v0 > 0.f ? v0*v0 : 0.f;
                    v1 = v1 > 0.f ? v1*v1 : 0.f;
                } else if (epi == 2) {
                    v0 = 15.f * tanhf(v0 * (1.f/15.f));
                    v1 = 15.f * tanhf(v1 * (1.f/15.f));
                }
                cp[0] = v0; cp[1] = v1;
            }
        }
    }
}

// generic GEMM kernel: grid = (N/128, M/128)
__global__ void __launch_bounds__(256)
sgemm_nt(const float* __restrict__ A, const float* __restrict__ B,
         float* __restrict__ C, int N, int K, int accum, int epi) {
    gemm_tile_tc(A, B, C, N, K, blockIdx.y*128, blockIdx.x*128, accum, epi);
}

// fused QKV: grid = (10, M/128). blocks 0-5 -> Q, 6-7 -> K, 8-9 -> V.
__global__ void __launch_bounds__(256)
qkv_gemm(const float* __restrict__ Wq, const float* __restrict__ Wk,
         const float* __restrict__ Wv) {
    int bx = blockIdx.x, row0 = blockIdx.y*128;
    const float* B; float* C; int N, col0;
    if (bx < 6)      { B = Wq; C = g_Q; N = DD;    col0 = bx*128; }
    else if (bx < 8) { B = Wk; C = g_K; N = KVDIM; col0 = (bx-6)*128; }
    else             { B = Wv; C = g_V; N = KVDIM; col0 = (bx-8)*128; }
    gemm_tile_tc(g_XN, B, C, N, DD, row0, col0, 0, 0);
}

// ---------------- value-embedding gate ----------------
__global__ void ve_kernel(int j, const int* __restrict__ idx,
                          const float* __restrict__ vet,
                          const float* __restrict__ veg) {
    int r = blockIdx.x;
    int h = threadIdx.x >> 5, lane = threadIdx.x & 31;
    float g = g_XN[(size_t)r*DD + lane] * veg[((size_t)j*KVHH + h)*32 + lane];
    #pragma unroll
    for (int o = 16; o > 0; o >>= 1) g += __shfl_xor_sync(0xffffffffu, g, o);
    float gate = 2.f / (1.f + expf(-g));
    const float* ve = vet + ((size_t)j*VV + idx[r])*KVDIM + h*HDIM;
    float* vp = g_V + (size_t)r*KVDIM + h*HDIM;
    vp[lane]      += gate * ve[lane];
    vp[lane + 32] += gate * ve[lane + 32];
}

// ---------------- RoPE + per-head RMSnorm ----------------
__global__ void rope_norm_kernel() {
    int r = blockIdx.x;
    int w = threadIdx.x >> 5, lane = threadIdx.x & 31;
    float* ptr;
    if (w < HH) ptr = g_Q + (size_t)r*DD    + w*HDIM;
    else        ptr = g_K + (size_t)r*KVDIM + (w - HH)*HDIM;
    int t = r % TT;
    float c = g_COS[t*32 + lane], s = g_SIN[t*32 + lane];
    float x1 = ptr[lane], x2 = ptr[lane + 32];
    float a =  x1*c + x2*s;
    float b = -x1*s + x2*c;
    float ss = a*a + b*b;
    #pragma unroll
    for (int o = 16; o > 0; o >>= 1) ss += __shfl_xor_sync(0xffffffffu, ss, o);
    float sc = rsqrtf(ss / HDIM + 1e-6f);
    ptr[lane]      = a * sc;
    ptr[lane + 32] = b * sc;
}

// ---------------- tiled sliding-window attention ----------------
__global__ void __launch_bounds__(256)
attn_kernel(int win) {
    int b = blockIdx.z, h = blockIdx.y, q0 = blockIdx.x * QT;
    int kvh = h / (HH / KVHH);
    __shared__ float Qs[QT][64];
    __shared__ float Ks[KT][66];
    __shared__ float Vs[KT][64];
    __shared__ float Ps[KT][65];
    int tid = threadIdx.x;
    int tx = tid & 15, ty = tid >> 4;

    for (int e = tid; e < QT*16; e += 256) {
        int q = e >> 4, d4 = e & 15;
        float4 v = *(const float4*)&g_Q[(size_t)(b*TT + q0 + q)*DD + h*HDIM + d4*4];
        Qs[q][d4*4+0] = v.x; Qs[q][d4*4+1] = v.y;
        Qs[q][d4*4+2] = v.z; Qs[q][d4*4+3] = v.w;
    }

    float m[4], l[4], o[4][4];
    #pragma unroll
    for (int i = 0; i < 4; i++) {
        m[i] = -1e30f; l[i] = 0.f;
        #pragma unroll
        for (int j = 0; j < 4; j++) o[i][j] = 0.f;
    }

    int klo = q0 - win + 1; if (klo < 0) klo = 0;
    int k_start = klo & ~(KT-1);

    for (int k0 = k_start; k0 < q0 + QT; k0 += KT) {
        for (int e = tid; e < KT*16; e += 256) {
            int k = e >> 4, d4 = e & 15;
            size_t row = (size_t)(b*TT + k0 + k)*KVDIM + kvh*HDIM;
            float4 kv = *(const float4*)&g_K[row + d4*4];
            float4 vv = *(const float4*)&g_V[row + d4*4];
            Ks[k][d4*4+0] = kv.x; Ks[k][d4*4+1] = kv.y;
            Ks[k][d4*4+2] = kv.z; Ks[k][d4*4+3] = kv.w;
            Vs[k][d4*4+0] = vv.x; Vs[k][d4*4+1] = vv.y;
            Vs[k][d4*4+2] = vv.z; Vs[k][d4*4+3] = vv.w;
        }
        __syncthreads();

        float s[4][2];
        #pragma unroll
        for (int i = 0; i < 4; i++) { s[i][0] = 0.f; s[i][1] = 0.f; }
        #pragma unroll 8
        for (int d = 0; d < 64; d++) {
            float k0v = Ks[tx*2+0][d];
            float k1v = Ks[tx*2+1][d];
            #pragma unroll
            for (int i = 0; i < 4; i++) {
                float qv = Qs[ty*4+i][d];
                s[i][0] += qv * k0v;
                s[i][1] += qv * k1v;
            }
        }
        #pragma unroll
        for (int i = 0; i < 4; i++) {
            int qg = q0 + ty*4 + i;
            #pragma unroll
            for (int j = 0; j < 2; j++) {
                int kg = k0 + tx*2 + j;
                int diff = qg - kg;
                bool valid = (diff >= 0) && (diff < win);
                s[i][j] = valid ? s[i][j] * 0.125f : -1e30f;
            }
        }
        #pragma unroll
        for (int i = 0; i < 4; i++) {
            float tmax = fmaxf(s[i][0], s[i][1]);
            #pragma unroll
            for (int off = 8; off > 0; off >>= 1)
                tmax = fmaxf(tmax, __shfl_xor_sync(0xffffffffu, tmax, off));
            float m_new = fmaxf(m[i], tmax);
            float p0 = (s[i][0] <= -1e29f) ? 0.f : expf(s[i][0] - m_new);
            float p1 = (s[i][1] <= -1e29f) ? 0.f : expf(s[i][1] - m_new);
            float tsum = p0 + p1;
            #pragma unroll
            for (int off = 8; off > 0; off >>= 1)
                tsum += __shfl_xor_sync(0xffffffffu, tsum, off);
            float scale = expf(m[i] - m_new);
            l[i] = l[i] * scale + tsum;
            #pragma unroll
            for (int j = 0; j < 4; j++) o[i][j] *= scale;
            m[i] = m_new;
            Ps[tx*2+0][ty*4+i] = p0;
            Ps[tx*2+1][ty*4+i] = p1;
        }
        __syncthreads();

        #pragma unroll 4
        for (int kk = 0; kk < KT; kk++) {
            float4 v4 = *(const float4*)&Vs[kk][tx*4];
            #pragma unroll
            for (int i = 0; i < 4; i++) {
                float p = Ps[kk][ty*4+i];
                o[i][0] += p * v4.x;
                o[i][1] += p * v4.y;
                o[i][2] += p * v4.z;
                o[i][3] += p * v4.w;
            }
        }
        __syncthreads();
    }

    #pragma unroll
    for (int i = 0; i < 4; i++) {
        float inv = 1.f / l[i];
        float4 v;
        v.x = o[i][0]*inv; v.y = o[i][1]*inv;
        v.z = o[i][2]*inv; v.w = o[i][3]*inv;
        *(float4*)&g_Y[(size_t)(b*TT + q0 + ty*4 + i)*DD + h*HDIM + tx*4] = v;
    }
}

// ---------------- host driver ----------------
extern "C" void kernel_launch(void* const* d_in, const int* in_sizes, int n_in,
                              void* d_out, int out_size) {
    const int*   idx  = (const int*)  d_in[0];
    const float* wte  = (const float*)d_in[1];
    const float* Wq   = (const float*)d_in[2];
    const float* Wk   = (const float*)d_in[3];
    const float* Wv   = (const float*)d_in[4];
    const float* Wo   = (const float*)d_in[5];
    const float* Wfc  = (const float*)d_in[6];
    const float* Wpr  = (const float*)d_in[7];
    const float* vet  = (const float*)d_in[8];
    const float* veg  = (const float*)d_in[9];
    const float* lamR = (const float*)d_in[10];
    const float* lamX = (const float*)d_in[11];
    const float* lmw  = (const float*)d_in[12];
    float* out = (float*)d_out;

    float *X, *XN, *Y, *Hb;
    cudaGetSymbolAddress((void**)&X,  g_X);
    cudaGetSymbolAddress((void**)&XN, g_XN);
    cudaGetSymbolAddress((void**)&Y,  g_Y);
    cudaGetSymbolAddress((void**)&Hb, g_H);

    static const int WINDOWS[LLAY] = {TT/2, TT, TT/2, TT, TT/2, TT};

    rotary_kernel<<<(TT*32 + 255)/256, 256>>>();
    embed_norm_kernel<<<NROWS, 256>>>(idx, wte);

    for (int i = 0; i < LLAY; i++) {
        resid_norm_kernel<<<NROWS, 256>>>(lamR, lamX, i);
        qkv_gemm<<<dim3(10, NROWS/128), 256>>>(Wq + (size_t)i*DD*DD,
                                               Wk + (size_t)i*KVDIM*DD,
                                               Wv + (size_t)i*KVDIM*DD);
        if (i == 1 || i == 3 || i == 5) {
            int j = (i - 1) / 2;
            ve_kernel<<<NROWS, KVHH*32>>>(j, idx, vet, veg);
        }
        rope_norm_kernel<<<NROWS, (HH + KVHH)*32>>>();
        attn_kernel<<<dim3(TT/QT, HH, BB), 256>>>(WINDOWS[i]);
        sgemm_nt<<<dim3(DD/128, NROWS/128), 256>>>(Y, Wo + (size_t)i*DD*DD, X, DD, DD, 1, 0);
        resid_norm_kernel<<<NROWS, 256>>>(lamR, lamX, -1);
        sgemm_nt<<<dim3(DFF/128, NROWS/128), 256>>>(XN, Wfc + (size_t)i*DFF*DD, Hb, DFF, DD, 0, 1);
        sgemm_nt<<<dim3(DD/128, NROWS/128), 256>>>(Hb, Wpr + (size_t)i*DD*DFF, X, DD, DFF, 1, 0);
    }

    resid_norm_kernel<<<NROWS, 256>>>(lamR, lamX, -1);
    sgemm_nt<<<dim3(VV/128, NROWS/128), 256>>>(XN, lmw, out, VV, DD, 0, 2);
}

// round 14
// speedup vs baseline: 4.5029x; 1.4642x over previous
#include <cuda_runtime.h>
#include <cuda_bf16.h>
#include <math.h>

// ---------------- problem constants ----------------
#define BB    2
#define TT    1024
#define DD    768
#define HH    12
#define KVHH  4
#define HDIM  64
#define KVDIM 256
#define LLAY  6
#define VV    32000
#define DFF   3072
#define NROWS (BB*TT)
#define QT    64
#define KT    32

// ---------------- device scratch (no allocs allowed) ----------------
__device__ float g_X [NROWS*DD];
__device__ float g_X0[NROWS*DD];
__device__ float g_XN[NROWS*DD];
__device__ float g_Q [NROWS*DD];
__device__ float g_K [NROWS*KVDIM];
__device__ float g_V [NROWS*KVDIM];
__device__ float g_Y [NROWS*DD];
__device__ float g_H [NROWS*DFF];
__device__ float g_COS[TT*32];
__device__ float g_SIN[TT*32];

// ---------------- rotary tables ----------------
__global__ void rotary_kernel() {
    int i = blockIdx.x * blockDim.x + threadIdx.x;
    if (i >= TT*32) return;
    int t = i >> 5, c = i & 31;
    double inv = exp(-((double)(2*c) / 64.0) * log(10000.0));
    double a = (double)t * inv;
    g_COS[i] = (float)cos(a);
    g_SIN[i] = (float)sin(a);
}

// ---------------- embedding + RMSnorm (x and x0) ----------------
__global__ void embed_norm_kernel(const int* __restrict__ idx,
                                  const float* __restrict__ wte) {
    int r = blockIdx.x;
    int t = threadIdx.x;
    const float* w = wte + (size_t)idx[r] * DD;
    float v0 = w[t], v1 = w[t+256], v2 = w[t+512];
    __shared__ float red[256];
    red[t] = v0*v0 + v1*v1 + v2*v2;
    __syncthreads();
    for (int s = 128; s > 0; s >>= 1) {
        if (t < s) red[t] += red[t+s];
        __syncthreads();
    }
    float sc = rsqrtf(red[0] / DD + 1e-6f);
    float* x  = g_X  + (size_t)r*DD;
    float* x0 = g_X0 + (size_t)r*DD;
    x[t]      = v0*sc;  x0[t]      = v0*sc;
    x[t+256]  = v1*sc;  x0[t+256]  = v1*sc;
    x[t+512]  = v2*sc;  x0[t+512]  = v2*sc;
}

// ---------------- residual mix + RMSnorm ----------------
__global__ void resid_norm_kernel(const float* __restrict__ lamR,
                                  const float* __restrict__ lamX, int layer) {
    int r = blockIdx.x;
    int t = threadIdx.x;
    float rl = 1.f, xl = 0.f;
    bool wr = (layer >= 0);
    if (wr) { rl = lamR[layer]; xl = lamX[layer]; }
    float* x  = g_X  + (size_t)r*DD;
    float* x0 = g_X0 + (size_t)r*DD;
    float* xn = g_XN + (size_t)r*DD;
    float v[3]; float ss = 0.f;
    #pragma unroll
    for (int p = 0; p < 3; p++) {
        int c = t + p*256;
        float v_ = rl * x[c] + xl * x0[c];
        v[p] = v_;
        ss += v_*v_;
    }
    __shared__ float red[256];
    red[t] = ss;
    __syncthreads();
    for (int s = 128; s > 0; s >>= 1) {
        if (t < s) red[t] += red[t+s];
        __syncthreads();
    }
    float sc = rsqrtf(red[0] / DD + 1e-6f);
    #pragma unroll
    for (int p = 0; p < 3; p++) {
        int c = t + p*256;
        if (wr) x[c] = v[p];
        xn[c] = v[p] * sc;
    }
}

// ---------------- bf16 split helpers ----------------
// pack 2 consecutive k-values (x=k even -> low 16, y=k odd -> high 16)
__device__ __forceinline__ void split2_bf16(float x, float y, unsigned& h, unsigned& l) {
    __nv_bfloat16 xh = __float2bfloat16_rn(x);
    __nv_bfloat16 yh = __float2bfloat16_rn(y);
    __nv_bfloat162 hp; hp.x = xh; hp.y = yh;
    h = *(unsigned*)&hp;
    __nv_bfloat162 lp;
    lp.x = __float2bfloat16_rn(x - __bfloat162float(xh));
    lp.y = __float2bfloat16_rn(y - __bfloat162float(yh));
    l = *(unsigned*)&lp;
}

__device__ __forceinline__ void mma_bf16(float c[4], const unsigned a[4], const unsigned b[2]) {
    asm volatile(
        "mma.sync.aligned.m16n8k16.row.col.f32.bf16.bf16.f32 "
        "{%0,%1,%2,%3}, {%4,%5,%6,%7}, {%8,%9}, {%0,%1,%2,%3};"
        : "+f"(c[0]), "+f"(c[1]), "+f"(c[2]), "+f"(c[3])
        : "r"(a[0]), "r"(a[1]), "r"(a[2]), "r"(a[3]), "r"(b[0]), "r"(b[1]));
}

// ---------------- tensor-core 128x128 GEMM tile (split-bf16): C (+)= A*B^T ----------------
// 256 thr = 8 warps (2 M x 4 N), warp tile 64x32, mma m16n8k16 bf16, K-tile 32.
// fp32 -> (hi,lo) bf16 planes at smem-store time; inner loop = pure LDS+MMA.
// 3-term product (hi*hi + hi*lo + lo*hi) ~= fp32 product to ~2^-18.
// smem: 4 planes of [128][40] bf16 (pad 8) -> conflict-free 32-bit fragment LDS.
// epi: 0 none, 1 relu^2, 2 softcap tanh. Dims: M%128==0, N%128==0, K%32==0.
__device__ __forceinline__ void gemm_tile_tc(
    const float* __restrict__ A, const float* __restrict__ B,
    float* __restrict__ C, int N, int K, int row0, int col0,
    int accum, int epi)
{
    __shared__ unsigned short AsH[128][40];
    __shared__ unsigned short AsL[128][40];
    __shared__ unsigned short BsH[128][40];
    __shared__ unsigned short BsL[128][40];
    int tid = threadIdx.x;
    int warp = tid >> 5, lane = tid & 31;
    int wm = warp >> 2, wn = warp & 3;           // warp origin (wm*64, wn*32)
    int gid = lane >> 2, tig = lane & 3;

    // loader coords: 128 rows x 8 float4 per matrix = 1024 -> 4 per thread
    int lrow[4], lk4[4];
    #pragma unroll
    for (int p = 0; p < 4; p++) {
        int e = tid + p*256;
        lrow[p] = e >> 3;
        lk4[p]  = e & 7;
    }

    float c[4][4][4];
    #pragma unroll
    for (int mt = 0; mt < 4; mt++)
        #pragma unroll
        for (int nt = 0; nt < 4; nt++)
            #pragma unroll
            for (int r = 0; r < 4; r++) c[mt][nt][r] = 0.f;

    float4 pa[4], pb[4];
    #pragma unroll
    for (int p = 0; p < 4; p++) {
        pa[p] = *(const float4*)&A[(size_t)(row0 + lrow[p])*K + lk4[p]*4];
        pb[p] = *(const float4*)&B[(size_t)(col0 + lrow[p])*K + lk4[p]*4];
    }

    for (int k0 = 0; k0 < K; k0 += 32) {
        #pragma unroll
        for (int p = 0; p < 4; p++) {
            unsigned h0, l0, h1, l1;
            split2_bf16(pa[p].x, pa[p].y, h0, l0);
            split2_bf16(pa[p].z, pa[p].w, h1, l1);
            *(uint2*)&AsH[lrow[p]][lk4[p]*4] = make_uint2(h0, h1);
            *(uint2*)&AsL[lrow[p]][lk4[p]*4] = make_uint2(l0, l1);
            split2_bf16(pb[p].x, pb[p].y, h0, l0);
            split2_bf16(pb[p].z, pb[p].w, h1, l1);
            *(uint2*)&BsH[lrow[p]][lk4[p]*4] = make_uint2(h0, h1);
            *(uint2*)&BsL[lrow[p]][lk4[p]*4] = make_uint2(l0, l1);
        }
        __syncthreads();
        if (k0 + 32 < K) {
            #pragma unroll
            for (int p = 0; p < 4; p++) {
                pa[p] = *(const float4*)&A[(size_t)(row0 + lrow[p])*K + k0 + 32 + lk4[p]*4];
                pb[p] = *(const float4*)&B[(size_t)(col0 + lrow[p])*K + k0 + 32 + lk4[p]*4];
            }
        }
        #pragma unroll
        for (int ch = 0; ch < 2; ch++) {
            int cb = ch*16 + tig*2;   // bf16 column of this thread's first k-pair
            unsigned ah[4][4], al[4][4], bh[4][2], bl[4][2];
            #pragma unroll
            for (int mt = 0; mt < 4; mt++) {
                int r = wm*64 + mt*16 + gid;
                ah[mt][0] = *(const unsigned*)&AsH[r  ][cb];
                ah[mt][1] = *(const unsigned*)&AsH[r+8][cb];
                ah[mt][2] = *(const unsigned*)&AsH[r  ][cb+8];
                ah[mt][3] = *(const unsigned*)&AsH[r+8][cb+8];
                al[mt][0] = *(const unsigned*)&AsL[r  ][cb];
                al[mt][1] = *(const unsigned*)&AsL[r+8][cb];
                al[mt][2] = *(const unsigned*)&AsL[r  ][cb+8];
                al[mt][3] = *(const unsigned*)&AsL[r+8][cb+8];
            }
            #pragma unroll
            for (int nt = 0; nt < 4; nt++) {
                int r = wn*32 + nt*8 + gid;
                bh[nt][0] = *(const unsigned*)&BsH[r][cb];
                bh[nt][1] = *(const unsigned*)&BsH[r][cb+8];
                bl[nt][0] = *(const unsigned*)&BsL[r][cb];
                bl[nt][1] = *(const unsigned*)&BsL[r][cb+8];
            }
            #pragma unroll
            for (int mt = 0; mt < 4; mt++)
                #pragma unroll
                for (int nt = 0; nt < 4; nt++) {
                    mma_bf16(c[mt][nt], ah[mt], bh[nt]);
                    mma_bf16(c[mt][nt], ah[mt], bl[nt]);
                    mma_bf16(c[mt][nt], al[mt], bh[nt]);
                }
        }
        __syncthreads();
    }

    // epilogue (same C layout as tf32 m16n8)
    #pragma unroll
    for (int mt = 0; mt < 4; mt++) {
        int rbase = row0 + wm*64 + mt*16 + gid;
        #pragma unroll
        for (int nt = 0; nt < 4; nt++) {
            int cc = col0 + wn*32 + nt*8 + tig*2;
            #pragma unroll
            for (int h = 0; h < 2; h++) {
                int r = rbase + h*8;
                float v0 = c[mt][nt][h*2+0];
                float v1 = c[mt][nt][h*2+1];
                float* cp = &C[(size_t)r*N + cc];
                if (accum) { v0 += cp[0]; v1 += cp[1]; }
                if (epi == 1) {
                    v0 = v0 > 0.f ? v0*v0 : 0.f;
                    v1 = v1 > 0.f ? v1*v1 : 0.f;
                } else if (epi == 2) {
                    v0 = 15.f * tanhf(v0 * (1.f/15.f));
                    v1 = 15.f * tanhf(v1 * (1.f/15.f));
                }
                cp[0] = v0; cp[1] = v1;
            }
        }
    }
}

// generic GEMM kernel: grid = (N/128, M/128)
__global__ void __launch_bounds__(256)
sgemm_nt(const float* __restrict__ A, const float* __restrict__ B,
         float* __restrict__ C, int N, int K, int accum, int epi) {
    gemm_tile_tc(A, B, C, N, K, blockIdx.y*128, blockIdx.x*128, accum, epi);
}

// fused QKV: grid = (10, M/128). blocks 0-5 -> Q, 6-7 -> K, 8-9 -> V.
__global__ void __launch_bounds__(256)
qkv_gemm(const float* __restrict__ Wq, const float* __restrict__ Wk,
         const float* __restrict__ Wv) {
    int bx = blockIdx.x, row0 = blockIdx.y*128;
    const float* B; float* C; int N, col0;
    if (bx < 6)      { B = Wq; C = g_Q; N = DD;    col0 = bx*128; }
    else if (bx < 8) { B = Wk; C = g_K; N = KVDIM; col0 = (bx-6)*128; }
    else             { B = Wv; C = g_V; N = KVDIM; col0 = (bx-8)*128; }
    gemm_tile_tc(g_XN, B, C, N, DD, row0, col0, 0, 0);
}

// ---------------- value-embedding gate ----------------
__global__ void ve_kernel(int j, const int* __restrict__ idx,
                          const float* __restrict__ vet,
                          const float* __restrict__ veg) {
    int r = blockIdx.x;
    int h = threadIdx.x >> 5, lane = threadIdx.x & 31;
    float g = g_XN[(size_t)r*DD + lane] * veg[((size_t)j*KVHH + h)*32 + lane];
    #pragma unroll
    for (int o = 16; o > 0; o >>= 1) g += __shfl_xor_sync(0xffffffffu, g, o);
    float gate = 2.f / (1.f + expf(-g));
    const float* ve = vet + ((size_t)j*VV + idx[r])*KVDIM + h*HDIM;
    float* vp = g_V + (size_t)r*KVDIM + h*HDIM;
    vp[lane]      += gate * ve[lane];
    vp[lane + 32] += gate * ve[lane + 32];
}

// ---------------- RoPE + per-head RMSnorm ----------------
__global__ void rope_norm_kernel() {
    int r = blockIdx.x;
    int w = threadIdx.x >> 5, lane = threadIdx.x & 31;
    float* ptr;
    if (w < HH) ptr = g_Q + (size_t)r*DD    + w*HDIM;
    else        ptr = g_K + (size_t)r*KVDIM + (w - HH)*HDIM;
    int t = r % TT;
    float c = g_COS[t*32 + lane], s = g_SIN[t*32 + lane];
    float x1 = ptr[lane], x2 = ptr[lane + 32];
    float a =  x1*c + x2*s;
    float b = -x1*s + x2*c;
    float ss = a*a + b*b;
    #pragma unroll
    for (int o = 16; o > 0; o >>= 1) ss += __shfl_xor_sync(0xffffffffu, ss, o);
    float sc = rsqrtf(ss / HDIM + 1e-6f);
    ptr[lane]      = a * sc;
    ptr[lane + 32] = b * sc;
}

// ---------------- tiled sliding-window attention ----------------
__global__ void __launch_bounds__(256)
attn_kernel(int win) {
    int b = blockIdx.z, h = blockIdx.y, q0 = blockIdx.x * QT;
    int kvh = h / (HH / KVHH);
    __shared__ float Qs[QT][64];
    __shared__ float Ks[KT][66];
    __shared__ float Vs[KT][64];
    __shared__ float Ps[KT][65];
    int tid = threadIdx.x;
    int tx = tid & 15, ty = tid >> 4;

    for (int e = tid; e < QT*16; e += 256) {
        int q = e >> 4, d4 = e & 15;
        float4 v = *(const float4*)&g_Q[(size_t)(b*TT + q0 + q)*DD + h*HDIM + d4*4];
        Qs[q][d4*4+0] = v.x; Qs[q][d4*4+1] = v.y;
        Qs[q][d4*4+2] = v.z; Qs[q][d4*4+3] = v.w;
    }

    float m[4], l[4], o[4][4];
    #pragma unroll
    for (int i = 0; i < 4; i++) {
        m[i] = -1e30f; l[i] = 0.f;
        #pragma unroll
        for (int j = 0; j < 4; j++) o[i][j] = 0.f;
    }

    int klo = q0 - win + 1; if (klo < 0) klo = 0;
    int k_start = klo & ~(KT-1);

    for (int k0 = k_start; k0 < q0 + QT; k0 += KT) {
        for (int e = tid; e < KT*16; e += 256) {
            int k = e >> 4, d4 = e & 15;
            size_t row = (size_t)(b*TT + k0 + k)*KVDIM + kvh*HDIM;
            float4 kv = *(const float4*)&g_K[row + d4*4];
            float4 vv = *(const float4*)&g_V[row + d4*4];
            Ks[k][d4*4+0] = kv.x; Ks[k][d4*4+1] = kv.y;
            Ks[k][d4*4+2] = kv.z; Ks[k][d4*4+3] = kv.w;
            Vs[k][d4*4+0] = vv.x; Vs[k][d4*4+1] = vv.y;
            Vs[k][d4*4+2] = vv.z; Vs[k][d4*4+3] = vv.w;
        }
        __syncthreads();

        float s[4][2];
        #pragma unroll
        for (int i = 0; i < 4; i++) { s[i][0] = 0.f; s[i][1] = 0.f; }
        #pragma unroll 8
        for (int d = 0; d < 64; d++) {
            float k0v = Ks[tx*2+0][d];
            float k1v = Ks[tx*2+1][d];
            #pragma unroll
            for (int i = 0; i < 4; i++) {
                float qv = Qs[ty*4+i][d];
                s[i][0] += qv * k0v;
                s[i][1] += qv * k1v;
            }
        }
        #pragma unroll
        for (int i = 0; i < 4; i++) {
            int qg = q0 + ty*4 + i;
            #pragma unroll
            for (int j = 0; j < 2; j++) {
                int kg = k0 + tx*2 + j;
                int diff = qg - kg;
                bool valid = (diff >= 0) && (diff < win);
                s[i][j] = valid ? s[i][j] * 0.125f : -1e30f;
            }
        }
        #pragma unroll
        for (int i = 0; i < 4; i++) {
            float tmax = fmaxf(s[i][0], s[i][1]);
            #pragma unroll
            for (int off = 8; off > 0; off >>= 1)
                tmax = fmaxf(tmax, __shfl_xor_sync(0xffffffffu, tmax, off));
            float m_new = fmaxf(m[i], tmax);
            float p0 = (s[i][0] <= -1e29f) ? 0.f : expf(s[i][0] - m_new);
            float p1 = (s[i][1] <= -1e29f) ? 0.f : expf(s[i][1] - m_new);
            float tsum = p0 + p1;
            #pragma unroll
            for (int off = 8; off > 0; off >>= 1)
                tsum += __shfl_xor_sync(0xffffffffu, tsum, off);
            float scale = expf(m[i] - m_new);
            l[i] = l[i] * scale + tsum;
            #pragma unroll
            for (int j = 0; j < 4; j++) o[i][j] *= scale;
            m[i] = m_new;
            Ps[tx*2+0][ty*4+i] = p0;
            Ps[tx*2+1][ty*4+i] = p1;
        }
        __syncthreads();

        #pragma unroll 4
        for (int kk = 0; kk < KT; kk++) {
            float4 v4 = *(const float4*)&Vs[kk][tx*4];
            #pragma unroll
            for (int i = 0; i < 4; i++) {
                float p = Ps[kk][ty*4+i];
                o[i][0] += p * v4.x;
                o[i][1] += p * v4.y;
                o[i][2] += p * v4.z;
                o[i][3] += p * v4.w;
            }
        }
        __syncthreads();
    }

    #pragma unroll
    for (int i = 0; i < 4; i++) {
        float inv = 1.f / l[i];
        float4 v;
        v.x = o[i][0]*inv; v.y = o[i][1]*inv;
        v.z = o[i][2]*inv; v.w = o[i][3]*inv;
        *(float4*)&g_Y[(size_t)(b*TT + q0 + ty*4 + i)*DD + h*HDIM + tx*4] = v;
    }
}

// ---------------- host driver ----------------
extern "C" void kernel_launch(void* const* d_in, const int* in_sizes, int n_in,
                              void* d_out, int out_size) {
    const int*   idx  = (const int*)  d_in[0];
    const float* wte  = (const float*)d_in[1];
    const float* Wq   = (const float*)d_in[2];
    const float* Wk   = (const float*)d_in[3];
    const float* Wv   = (const float*)d_in[4];
    const float* Wo   = (const float*)d_in[5];
    const float* Wfc  = (const float*)d_in[6];
    const float* Wpr  = (const float*)d_in[7];
    const float* vet  = (const float*)d_in[8];
    const float* veg  = (const float*)d_in[9];
    const float* lamR = (const float*)d_in[10];
    const float* lamX = (const float*)d_in[11];
    const float* lmw  = (const float*)d_in[12];
    float* out = (float*)d_out;

    float *X, *XN, *Y, *Hb;
    cudaGetSymbolAddress((void**)&X,  g_X);
    cudaGetSymbolAddress((void**)&XN, g_XN);
    cudaGetSymbolAddress((void**)&Y,  g_Y);
    cudaGetSymbolAddress((void**)&Hb, g_H);

    static const int WINDOWS[LLAY] = {TT/2, TT, TT/2, TT, TT/2, TT};

    rotary_kernel<<<(TT*32 + 255)/256, 256>>>();
    embed_norm_kernel<<<NROWS, 256>>>(idx, wte);

    for (int i = 0; i < LLAY; i++) {
        resid_norm_kernel<<<NROWS, 256>>>(lamR, lamX, i);
        qkv_gemm<<<dim3(10, NROWS/128), 256>>>(Wq + (size_t)i*DD*DD,
                                               Wk + (size_t)i*KVDIM*DD,
                                               Wv + (size_t)i*KVDIM*DD);
        if (i == 1 || i == 3 || i == 5) {
            int j = (i - 1) / 2;
            ve_kernel<<<NROWS, KVHH*32>>>(j, idx, vet, veg);
        }
        rope_norm_kernel<<<NROWS, (HH + KVHH)*32>>>();
        attn_kernel<<<dim3(TT/QT, HH, BB), 256>>>(WINDOWS[i]);
        sgemm_nt<<<dim3(DD/128, NROWS/128), 256>>>(Y, Wo + (size_t)i*DD*DD, X, DD, DD, 1, 0);
        resid_norm_kernel<<<NROWS, 256>>>(lamR, lamX, -1);
        sgemm_nt<<<dim3(DFF/128, NROWS/128), 256>>>(XN, Wfc + (size_t)i*DFF*DD, Hb, DFF, DD, 0, 1);
        sgemm_nt<<<dim3(DD/128, NROWS/128), 256>>>(Hb, Wpr + (size_t)i*DD*DFF, X, DD, DFF, 1, 0);
    }

    resid_norm_kernel<<<NROWS, 256>>>(lamR, lamX, -1);
    sgemm_nt<<<dim3(VV/128, NROWS/128), 256>>>(XN, lmw, out, VV, DD, 0, 2);
}